// round 10
// baseline (speedup 1.0000x reference)
#include <cuda_runtime.h>
#include <cuda_fp16.h>
#include <stdint.h>
#include <math.h>

// FBPINN via mma.sync m16n8k16 (fp16 in, fp32 acc), sm_103-safe PTX.
// R9 = R5 structure (8 warps x 16 pts, full 128 neurons/warp) +
//   - hardware tanh.approx.f32 (MUFU.TANH) epilogues
//   - paired-independent MMA issue order (j/j+1 interleaved across terms)
// 2-term precision split (A_hi*B_hi + A_hi*B_lo). cp.async double buffer.

#define NSUB 16
#define WID  128
#define NHID 3
#define NSL  (NSUB*NHID)       // 48
#define NPTS 65536
#define NP   128               // points per CTA
#define THREADS 256            // 8 warps x 16 points
#define NCTAS (NPTS/NP)        // 512

#define W_SLOT_BYTES 65536
#define SM_XS (2*W_SLOT_BYTES)
#define SMEM_TOTAL (SM_XS + NP*4)

// Fragment-packed weights: [sl][j(16)][k(8)][lane(32)] x uint4{Bhi0,Bhi1,Blo0,Blo1}
__device__ uint4 g_Wpk[NSL*4096];

// ---------------- helpers ----------------
__device__ __forceinline__ uint32_t smem_u32(const void* p) {
    uint32_t a;
    asm("{ .reg .u64 t; cvta.to.shared.u64 t, %1; cvt.u32.u64 %0, t; }" : "=r"(a) : "l"(p));
    return a;
}
__device__ __forceinline__ float tanhA(float x) {
    float y;
    asm("tanh.approx.f32 %0, %1;" : "=f"(y) : "f"(x));
    return y;
}
__device__ __forceinline__ float fast_sigmoid(float z) {
    return __fdividef(1.0f, 1.0f + __expf(-z));
}
__device__ __forceinline__ uint32_t pack_hi(float f0, float f1) {
    __half2 h = __floats2half2_rn(f0, f1);
    return *reinterpret_cast<uint32_t*>(&h);
}

#define MMA16816(c, a, b0, b1) \
    asm volatile("mma.sync.aligned.m16n8k16.row.col.f32.f16.f16.f32 " \
        "{%0,%1,%2,%3}, {%4,%5,%6,%7}, {%8,%9}, {%0,%1,%2,%3};" \
        : "+f"((c)[0]), "+f"((c)[1]), "+f"((c)[2]), "+f"((c)[3]) \
        : "r"((a)[0]), "r"((a)[1]), "r"((a)[2]), "r"((a)[3]), "r"(b0), "r"(b1))

#define CP_ASYNC16(dst, src) \
    asm volatile("cp.async.cg.shared.global [%0], [%1], 16;" :: "r"(dst), "l"(src) : "memory")
#define CP_COMMIT() asm volatile("cp.async.commit_group;" ::: "memory")
#define CP_WAIT1()  asm volatile("cp.async.wait_group 1;" ::: "memory")

// ---------------- prep: pack weights into fragment order, fp16 hi/lo ----------------
__global__ void prep_pack(const float* __restrict__ Wh) {
    int idx = blockIdx.x * blockDim.x + threadIdx.x;   // < NSL*16*8*32
    int lane = idx & 31;
    int k    = (idx >> 5) & 7;
    int j    = (idx >> 8) & 15;
    int sl   = idx >> 12;
    int g = lane >> 2, t = lane & 3;
    int v = 8 * j + g;              // neuron (n of the mma)
    int w = 16 * k + 2 * t;         // input index (k of the mma)
    const float* row = Wh + ((size_t)sl * WID + v) * WID;
    float w0 = row[w], w1 = row[w + 1], w8 = row[w + 8], w9 = row[w + 9];

    __half2 h01 = __floats2half2_rn(w0, w1);
    __half2 h89 = __floats2half2_rn(w8, w9);
    float l0 = w0 - __low2float(h01), l1 = w1 - __high2float(h01);
    float l8 = w8 - __low2float(h89), l9 = w9 - __high2float(h89);
    __half2 lo01 = __floats2half2_rn(l0, l1);
    __half2 lo89 = __floats2half2_rn(l8, l9);

    uint4 o;
    o.x = *reinterpret_cast<uint32_t*>(&h01);
    o.y = *reinterpret_cast<uint32_t*>(&h89);
    o.z = *reinterpret_cast<uint32_t*>(&lo01);
    o.w = *reinterpret_cast<uint32_t*>(&lo89);
    g_Wpk[idx] = o;
}

// ---------------- stage one layer's packed weights via cp.async ----------------
__device__ __forceinline__ void stage_W(int sl, uint32_t dst_base, int tid) {
    const uint4* src = g_Wpk + (size_t)sl * 4096 + tid;
    uint32_t dst = dst_base + (uint32_t)tid * 16;
    #pragma unroll
    for (int i = 0; i < 16; i++) {
        CP_ASYNC16(dst + (uint32_t)i * 4096u, src + i * 256);
    }
}

// ---------------- main kernel ----------------
__global__ void __launch_bounds__(THREADS, 1) fbpinn_mma_kernel(
    const float* __restrict__ x,
    const float* __restrict__ W0,      // [16,128]
    const float* __restrict__ b0,      // [16,128]
    const float* __restrict__ bh,      // [16,3,128]
    const float* __restrict__ Wout,    // [16,128]
    const float* __restrict__ bout,    // [16]
    const float* __restrict__ centres,
    const float* __restrict__ scales,
    const float* __restrict__ mu_min,
    const float* __restrict__ sd_min,
    const float* __restrict__ mu_max,
    const float* __restrict__ sd_max,
    float* __restrict__ out)
{
    extern __shared__ char smem[];
    const uint32_t sb = smem_u32(smem);
    float* xs = (float*)(smem + SM_XS);

    const int tid  = threadIdx.x;
    const int lane = tid & 31;
    const int w    = tid >> 5;        // warp 0..7
    const int g    = lane >> 2;       // 0..7
    const int t    = lane & 3;        // 0..3
    const int pblk = blockIdx.x * NP;
    const int r0 = w * 16 + g;        // point row (local)
    const int r1 = r0 + 8;

    if (tid < NP) xs[tid] = x[pblk + tid];

    // Prologue: stage sl=0 and sl=1
    stage_W(0, sb, tid);                 CP_COMMIT();
    stage_W(1, sb + W_SLOT_BYTES, tid);  CP_COMMIT();
    __syncthreads();   // xs visible

    const float x0v = xs[r0];
    const float x1v = xs[r1];

    float res0 = 0.0f, res1 = 0.0f;

    uint32_t Ahi[8][4];

    for (int s = 0; s < NSUB; s++) {
        const float centre = __ldg(&centres[s]);
        const float inv_scale = 1.0f / fmaxf(__ldg(&scales[s]), 1e-8f);
        const float xi0 = (x0v - centre) * inv_scale;
        const float xi1 = (x1v - centre) * inv_scale;

        // ---- layer 0: build A fragments directly ----
        const float* W0p = W0 + s * WID;
        const float* b0p = b0 + s * WID;
        #pragma unroll
        for (int kf = 0; kf < 8; kf++) {
            const int vb = 16 * kf + 2 * t;
            const float wv0 = __ldg(&W0p[vb]),     bv0 = __ldg(&b0p[vb]);
            const float wv1 = __ldg(&W0p[vb + 1]), bv1 = __ldg(&b0p[vb + 1]);
            const float wv8 = __ldg(&W0p[vb + 8]), bv8 = __ldg(&b0p[vb + 8]);
            const float wv9 = __ldg(&W0p[vb + 9]), bv9 = __ldg(&b0p[vb + 9]);
            Ahi[kf][0] = pack_hi(tanhA(fmaf(wv0, xi0, bv0)), tanhA(fmaf(wv1, xi0, bv1)));
            Ahi[kf][1] = pack_hi(tanhA(fmaf(wv0, xi1, bv0)), tanhA(fmaf(wv1, xi1, bv1)));
            Ahi[kf][2] = pack_hi(tanhA(fmaf(wv8, xi0, bv8)), tanhA(fmaf(wv9, xi0, bv9)));
            Ahi[kf][3] = pack_hi(tanhA(fmaf(wv8, xi1, bv8)), tanhA(fmaf(wv9, xi1, bv9)));
        }

        // ---- hidden layers ----
        for (int l = 0; l < NHID; l++) {
            const int sl = s * NHID + l;
            const uint32_t slot = sb + (uint32_t)(sl & 1) * W_SLOT_BYTES;

            CP_WAIT1();
            __syncthreads();

            // init acc with bias
            float acc[16][4];
            const float* bhp = bh + sl * WID;
            #pragma unroll
            for (int j = 0; j < 16; j++) {
                const float bv0 = __ldg(&bhp[8 * j + 2 * t]);
                const float bv1 = __ldg(&bhp[8 * j + 2 * t + 1]);
                acc[j][0] = bv0; acc[j][1] = bv1; acc[j][2] = bv0; acc[j][3] = bv1;
            }

            // GEMM: 16 n-tiles x 8 k-steps x 2 terms.
            // Pairs (j, j+1) processed together so consecutive MMAs are independent,
            // with a 2-fragment lookahead to cover LDS latency.
            const uint32_t bbase = (uint32_t)(slot - sb) + ((uint32_t)lane << 4);
            uint4 f0 = *(const uint4*)((const char*)smem + bbase);                 // (j=0,k=0)
            uint4 f1 = *(const uint4*)((const char*)smem + bbase + (1u * 8u << 9)); // (j=1,k=0)
            #pragma unroll
            for (int k = 0; k < 8; k++) {
                #pragma unroll
                for (int j = 0; j < 16; j += 2) {
                    const uint4 c0 = f0, c1 = f1;
                    // next pair: (j+2, k) or (0, k+1); harmless wrap at the very end
                    const int nj = (j == 14) ? 0 : (j + 2);
                    const int nk = (j == 14) ? (k == 7 ? 0 : k + 1) : k;
                    f0 = *(const uint4*)((const char*)smem + bbase + (uint32_t)(((nj    ) * 8 + nk) << 9));
                    f1 = *(const uint4*)((const char*)smem + bbase + (uint32_t)(((nj + 1) * 8 + nk) << 9));
                    MMA16816(acc[j],     Ahi[k], c0.x, c0.y);
                    MMA16816(acc[j + 1], Ahi[k], c1.x, c1.y);
                    MMA16816(acc[j],     Ahi[k], c0.z, c0.w);
                    MMA16816(acc[j + 1], Ahi[k], c1.z, c1.w);
                }
            }

            __syncthreads();   // all warps done reading this slot
            if (sl + 2 < NSL) stage_W(sl + 2, slot, tid);
            CP_COMMIT();

            if (l < NHID - 1) {
                // epilogue: hardware tanh -> fp16 -> next A fragments
                #pragma unroll
                for (int kf = 0; kf < 8; kf++) {
                    const int j0 = 2 * kf, j1 = 2 * kf + 1;
                    Ahi[kf][0] = pack_hi(tanhA(acc[j0][0]), tanhA(acc[j0][1]));
                    Ahi[kf][1] = pack_hi(tanhA(acc[j0][2]), tanhA(acc[j0][3]));
                    Ahi[kf][2] = pack_hi(tanhA(acc[j1][0]), tanhA(acc[j1][1]));
                    Ahi[kf][3] = pack_hi(tanhA(acc[j1][2]), tanhA(acc[j1][3]));
                }
            } else {
                // final: fold output layer + window
                float p0 = 0.0f, p1 = 0.0f;
                const float* wop = Wout + s * WID;
                #pragma unroll
                for (int j = 0; j < 16; j++) {
                    const float wv0 = __ldg(&wop[8 * j + 2 * t]);
                    const float wv1 = __ldg(&wop[8 * j + 2 * t + 1]);
                    p0 = fmaf(wv0, tanhA(acc[j][0]), p0);
                    p0 = fmaf(wv1, tanhA(acc[j][1]), p0);
                    p1 = fmaf(wv0, tanhA(acc[j][2]), p1);
                    p1 = fmaf(wv1, tanhA(acc[j][3]), p1);
                }
                p0 += __shfl_xor_sync(0xFFFFFFFF, p0, 1);
                p0 += __shfl_xor_sync(0xFFFFFFFF, p0, 2);
                p1 += __shfl_xor_sync(0xFFFFFFFF, p1, 1);
                p1 += __shfl_xor_sync(0xFFFFFFFF, p1, 2);

                const float bo = __ldg(&bout[s]);
                const float mmin = __ldg(&mu_min[s]), smin = __ldg(&sd_min[s]);
                const float mmax = __ldg(&mu_max[s]), smax = __ldg(&sd_max[s]);
                const float wm0 = fast_sigmoid((x0v - mmin) / smin) *
                                  fast_sigmoid((mmax - x0v) / smax);
                const float wm1 = fast_sigmoid((x1v - mmin) / smin) *
                                  fast_sigmoid((mmax - x1v) / smax);
                res0 = fmaf(wm0, p0 + bo, res0);
                res1 = fmaf(wm1, p1 + bo, res1);
            }
        }
    }

    if (t == 0) {
        out[pblk + r0] = res0;
        out[pblk + r1] = res1;
    }
}

// ---------------- launch ----------------
extern "C" void kernel_launch(void* const* d_in, const int* in_sizes, int n_in,
                              void* d_out, int out_size) {
    const float* x       = (const float*)d_in[0];
    const float* W0      = (const float*)d_in[1];
    const float* b0      = (const float*)d_in[2];
    const float* Wh      = (const float*)d_in[3];
    const float* bh      = (const float*)d_in[4];
    const float* Wout    = (const float*)d_in[5];
    const float* bout    = (const float*)d_in[6];
    const float* centres = (const float*)d_in[7];
    const float* scales  = (const float*)d_in[8];
    const float* mu_min  = (const float*)d_in[9];
    const float* sd_min  = (const float*)d_in[10];
    const float* mu_max  = (const float*)d_in[11];
    const float* sd_max  = (const float*)d_in[12];
    float* out = (float*)d_out;

    cudaFuncSetAttribute(fbpinn_mma_kernel,
                         cudaFuncAttributeMaxDynamicSharedMemorySize, SMEM_TOTAL);

    prep_pack<<<(NSL * 4096) / 256, 256>>>(Wh);

    fbpinn_mma_kernel<<<NCTAS, THREADS, SMEM_TOTAL>>>(
        x, W0, b0, bh, Wout, bout, centres, scales,
        mu_min, sd_min, mu_max, sd_max, out);
}

// round 11
// speedup vs baseline: 1.0004x; 1.0004x over previous
#include <cuda_runtime.h>
#include <cuda_fp16.h>
#include <stdint.h>
#include <math.h>

// FBPINN via mma.sync m16n8k16 (fp16 in, fp32 acc), sm_103-safe PTX.
// R9 = R5 structure (8 warps x 16 pts, full 128 neurons/warp) +
//   - hardware tanh.approx.f32 (MUFU.TANH) epilogues
//   - paired-independent MMA issue order (j/j+1 interleaved across terms)
// 2-term precision split (A_hi*B_hi + A_hi*B_lo). cp.async double buffer.

#define NSUB 16
#define WID  128
#define NHID 3
#define NSL  (NSUB*NHID)       // 48
#define NPTS 65536
#define NP   128               // points per CTA
#define THREADS 256            // 8 warps x 16 points
#define NCTAS (NPTS/NP)        // 512

#define W_SLOT_BYTES 65536
#define SM_XS (2*W_SLOT_BYTES)
#define SMEM_TOTAL (SM_XS + NP*4)

// Fragment-packed weights: [sl][j(16)][k(8)][lane(32)] x uint4{Bhi0,Bhi1,Blo0,Blo1}
__device__ uint4 g_Wpk[NSL*4096];

// ---------------- helpers ----------------
__device__ __forceinline__ uint32_t smem_u32(const void* p) {
    uint32_t a;
    asm("{ .reg .u64 t; cvta.to.shared.u64 t, %1; cvt.u32.u64 %0, t; }" : "=r"(a) : "l"(p));
    return a;
}
__device__ __forceinline__ float tanhA(float x) {
    float y;
    asm("tanh.approx.f32 %0, %1;" : "=f"(y) : "f"(x));
    return y;
}
__device__ __forceinline__ float fast_sigmoid(float z) {
    return __fdividef(1.0f, 1.0f + __expf(-z));
}
__device__ __forceinline__ uint32_t pack_hi(float f0, float f1) {
    __half2 h = __floats2half2_rn(f0, f1);
    return *reinterpret_cast<uint32_t*>(&h);
}

#define MMA16816(c, a, b0, b1) \
    asm volatile("mma.sync.aligned.m16n8k16.row.col.f32.f16.f16.f32 " \
        "{%0,%1,%2,%3}, {%4,%5,%6,%7}, {%8,%9}, {%0,%1,%2,%3};" \
        : "+f"((c)[0]), "+f"((c)[1]), "+f"((c)[2]), "+f"((c)[3]) \
        : "r"((a)[0]), "r"((a)[1]), "r"((a)[2]), "r"((a)[3]), "r"(b0), "r"(b1))

#define CP_ASYNC16(dst, src) \
    asm volatile("cp.async.cg.shared.global [%0], [%1], 16;" :: "r"(dst), "l"(src) : "memory")
#define CP_COMMIT() asm volatile("cp.async.commit_group;" ::: "memory")
#define CP_WAIT1()  asm volatile("cp.async.wait_group 1;" ::: "memory")

// ---------------- prep: pack weights into fragment order, fp16 hi/lo ----------------
__global__ void prep_pack(const float* __restrict__ Wh) {
    int idx = blockIdx.x * blockDim.x + threadIdx.x;   // < NSL*16*8*32
    int lane = idx & 31;
    int k    = (idx >> 5) & 7;
    int j    = (idx >> 8) & 15;
    int sl   = idx >> 12;
    int g = lane >> 2, t = lane & 3;
    int v = 8 * j + g;              // neuron (n of the mma)
    int w = 16 * k + 2 * t;         // input index (k of the mma)
    const float* row = Wh + ((size_t)sl * WID + v) * WID;
    float w0 = row[w], w1 = row[w + 1], w8 = row[w + 8], w9 = row[w + 9];

    __half2 h01 = __floats2half2_rn(w0, w1);
    __half2 h89 = __floats2half2_rn(w8, w9);
    float l0 = w0 - __low2float(h01), l1 = w1 - __high2float(h01);
    float l8 = w8 - __low2float(h89), l9 = w9 - __high2float(h89);
    __half2 lo01 = __floats2half2_rn(l0, l1);
    __half2 lo89 = __floats2half2_rn(l8, l9);

    uint4 o;
    o.x = *reinterpret_cast<uint32_t*>(&h01);
    o.y = *reinterpret_cast<uint32_t*>(&h89);
    o.z = *reinterpret_cast<uint32_t*>(&lo01);
    o.w = *reinterpret_cast<uint32_t*>(&lo89);
    g_Wpk[idx] = o;
}

// ---------------- stage one layer's packed weights via cp.async ----------------
__device__ __forceinline__ void stage_W(int sl, uint32_t dst_base, int tid) {
    const uint4* src = g_Wpk + (size_t)sl * 4096 + tid;
    uint32_t dst = dst_base + (uint32_t)tid * 16;
    #pragma unroll
    for (int i = 0; i < 16; i++) {
        CP_ASYNC16(dst + (uint32_t)i * 4096u, src + i * 256);
    }
}

// ---------------- main kernel ----------------
__global__ void __launch_bounds__(THREADS, 1) fbpinn_mma_kernel(
    const float* __restrict__ x,
    const float* __restrict__ W0,      // [16,128]
    const float* __restrict__ b0,      // [16,128]
    const float* __restrict__ bh,      // [16,3,128]
    const float* __restrict__ Wout,    // [16,128]
    const float* __restrict__ bout,    // [16]
    const float* __restrict__ centres,
    const float* __restrict__ scales,
    const float* __restrict__ mu_min,
    const float* __restrict__ sd_min,
    const float* __restrict__ mu_max,
    const float* __restrict__ sd_max,
    float* __restrict__ out)
{
    extern __shared__ char smem[];
    const uint32_t sb = smem_u32(smem);
    float* xs = (float*)(smem + SM_XS);

    const int tid  = threadIdx.x;
    const int lane = tid & 31;
    const int w    = tid >> 5;        // warp 0..7
    const int g    = lane >> 2;       // 0..7
    const int t    = lane & 3;        // 0..3
    const int pblk = blockIdx.x * NP;
    const int r0 = w * 16 + g;        // point row (local)
    const int r1 = r0 + 8;

    if (tid < NP) xs[tid] = x[pblk + tid];

    // Prologue: stage sl=0 and sl=1
    stage_W(0, sb, tid);                 CP_COMMIT();
    stage_W(1, sb + W_SLOT_BYTES, tid);  CP_COMMIT();
    __syncthreads();   // xs visible

    const float x0v = xs[r0];
    const float x1v = xs[r1];

    float res0 = 0.0f, res1 = 0.0f;

    uint32_t Ahi[8][4];

    for (int s = 0; s < NSUB; s++) {
        const float centre = __ldg(&centres[s]);
        const float inv_scale = 1.0f / fmaxf(__ldg(&scales[s]), 1e-8f);
        const float xi0 = (x0v - centre) * inv_scale;
        const float xi1 = (x1v - centre) * inv_scale;

        // ---- layer 0: build A fragments directly ----
        const float* W0p = W0 + s * WID;
        const float* b0p = b0 + s * WID;
        #pragma unroll
        for (int kf = 0; kf < 8; kf++) {
            const int vb = 16 * kf + 2 * t;
            const float wv0 = __ldg(&W0p[vb]),     bv0 = __ldg(&b0p[vb]);
            const float wv1 = __ldg(&W0p[vb + 1]), bv1 = __ldg(&b0p[vb + 1]);
            const float wv8 = __ldg(&W0p[vb + 8]), bv8 = __ldg(&b0p[vb + 8]);
            const float wv9 = __ldg(&W0p[vb + 9]), bv9 = __ldg(&b0p[vb + 9]);
            Ahi[kf][0] = pack_hi(tanhA(fmaf(wv0, xi0, bv0)), tanhA(fmaf(wv1, xi0, bv1)));
            Ahi[kf][1] = pack_hi(tanhA(fmaf(wv0, xi1, bv0)), tanhA(fmaf(wv1, xi1, bv1)));
            Ahi[kf][2] = pack_hi(tanhA(fmaf(wv8, xi0, bv8)), tanhA(fmaf(wv9, xi0, bv9)));
            Ahi[kf][3] = pack_hi(tanhA(fmaf(wv8, xi1, bv8)), tanhA(fmaf(wv9, xi1, bv9)));
        }

        // ---- hidden layers ----
        for (int l = 0; l < NHID; l++) {
            const int sl = s * NHID + l;
            const uint32_t slot = sb + (uint32_t)(sl & 1) * W_SLOT_BYTES;

            CP_WAIT1();
            __syncthreads();

            // init acc with bias
            float acc[16][4];
            const float* bhp = bh + sl * WID;
            #pragma unroll
            for (int j = 0; j < 16; j++) {
                const float bv0 = __ldg(&bhp[8 * j + 2 * t]);
                const float bv1 = __ldg(&bhp[8 * j + 2 * t + 1]);
                acc[j][0] = bv0; acc[j][1] = bv1; acc[j][2] = bv0; acc[j][3] = bv1;
            }

            // GEMM: 16 n-tiles x 8 k-steps x 2 terms.
            // Pairs (j, j+1) processed together so consecutive MMAs are independent,
            // with a 2-fragment lookahead to cover LDS latency.
            const uint32_t bbase = (uint32_t)(slot - sb) + ((uint32_t)lane << 4);
            uint4 f0 = *(const uint4*)((const char*)smem + bbase);                 // (j=0,k=0)
            uint4 f1 = *(const uint4*)((const char*)smem + bbase + (1u * 8u << 9)); // (j=1,k=0)
            #pragma unroll
            for (int k = 0; k < 8; k++) {
                #pragma unroll
                for (int j = 0; j < 16; j += 2) {
                    const uint4 c0 = f0, c1 = f1;
                    // next pair: (j+2, k) or (0, k+1); harmless wrap at the very end
                    const int nj = (j == 14) ? 0 : (j + 2);
                    const int nk = (j == 14) ? (k == 7 ? 0 : k + 1) : k;
                    f0 = *(const uint4*)((const char*)smem + bbase + (uint32_t)(((nj    ) * 8 + nk) << 9));
                    f1 = *(const uint4*)((const char*)smem + bbase + (uint32_t)(((nj + 1) * 8 + nk) << 9));
                    MMA16816(acc[j],     Ahi[k], c0.x, c0.y);
                    MMA16816(acc[j + 1], Ahi[k], c1.x, c1.y);
                    MMA16816(acc[j],     Ahi[k], c0.z, c0.w);
                    MMA16816(acc[j + 1], Ahi[k], c1.z, c1.w);
                }
            }

            __syncthreads();   // all warps done reading this slot
            if (sl + 2 < NSL) stage_W(sl + 2, slot, tid);
            CP_COMMIT();

            if (l < NHID - 1) {
                // epilogue: hardware tanh -> fp16 -> next A fragments
                #pragma unroll
                for (int kf = 0; kf < 8; kf++) {
                    const int j0 = 2 * kf, j1 = 2 * kf + 1;
                    Ahi[kf][0] = pack_hi(tanhA(acc[j0][0]), tanhA(acc[j0][1]));
                    Ahi[kf][1] = pack_hi(tanhA(acc[j0][2]), tanhA(acc[j0][3]));
                    Ahi[kf][2] = pack_hi(tanhA(acc[j1][0]), tanhA(acc[j1][1]));
                    Ahi[kf][3] = pack_hi(tanhA(acc[j1][2]), tanhA(acc[j1][3]));
                }
            } else {
                // final: fold output layer + window
                float p0 = 0.0f, p1 = 0.0f;
                const float* wop = Wout + s * WID;
                #pragma unroll
                for (int j = 0; j < 16; j++) {
                    const float wv0 = __ldg(&wop[8 * j + 2 * t]);
                    const float wv1 = __ldg(&wop[8 * j + 2 * t + 1]);
                    p0 = fmaf(wv0, tanhA(acc[j][0]), p0);
                    p0 = fmaf(wv1, tanhA(acc[j][1]), p0);
                    p1 = fmaf(wv0, tanhA(acc[j][2]), p1);
                    p1 = fmaf(wv1, tanhA(acc[j][3]), p1);
                }
                p0 += __shfl_xor_sync(0xFFFFFFFF, p0, 1);
                p0 += __shfl_xor_sync(0xFFFFFFFF, p0, 2);
                p1 += __shfl_xor_sync(0xFFFFFFFF, p1, 1);
                p1 += __shfl_xor_sync(0xFFFFFFFF, p1, 2);

                const float bo = __ldg(&bout[s]);
                const float mmin = __ldg(&mu_min[s]), smin = __ldg(&sd_min[s]);
                const float mmax = __ldg(&mu_max[s]), smax = __ldg(&sd_max[s]);
                const float wm0 = fast_sigmoid((x0v - mmin) / smin) *
                                  fast_sigmoid((mmax - x0v) / smax);
                const float wm1 = fast_sigmoid((x1v - mmin) / smin) *
                                  fast_sigmoid((mmax - x1v) / smax);
                res0 = fmaf(wm0, p0 + bo, res0);
                res1 = fmaf(wm1, p1 + bo, res1);
            }
        }
    }

    if (t == 0) {
        out[pblk + r0] = res0;
        out[pblk + r1] = res1;
    }
}

// ---------------- launch ----------------
extern "C" void kernel_launch(void* const* d_in, const int* in_sizes, int n_in,
                              void* d_out, int out_size) {
    const float* x       = (const float*)d_in[0];
    const float* W0      = (const float*)d_in[1];
    const float* b0      = (const float*)d_in[2];
    const float* Wh      = (const float*)d_in[3];
    const float* bh      = (const float*)d_in[4];
    const float* Wout    = (const float*)d_in[5];
    const float* bout    = (const float*)d_in[6];
    const float* centres = (const float*)d_in[7];
    const float* scales  = (const float*)d_in[8];
    const float* mu_min  = (const float*)d_in[9];
    const float* sd_min  = (const float*)d_in[10];
    const float* mu_max  = (const float*)d_in[11];
    const float* sd_max  = (const float*)d_in[12];
    float* out = (float*)d_out;

    cudaFuncSetAttribute(fbpinn_mma_kernel,
                         cudaFuncAttributeMaxDynamicSharedMemorySize, SMEM_TOTAL);

    prep_pack<<<(NSL * 4096) / 256, 256>>>(Wh);

    fbpinn_mma_kernel<<<NCTAS, THREADS, SMEM_TOTAL>>>(
        x, W0, b0, bh, Wout, bout, centres, scales,
        mu_min, sd_min, mu_max, sd_max, out);
}

// round 12
// speedup vs baseline: 1.0019x; 1.0015x over previous
#include <cuda_runtime.h>
#include <cuda_fp16.h>
#include <stdint.h>
#include <math.h>

// FBPINN via mma.sync m16n8k16 (fp16 in, fp32 acc), sm_103-safe PTX.
// R9 = R5 structure (8 warps x 16 pts, full 128 neurons/warp) +
//   - hardware tanh.approx.f32 (MUFU.TANH) epilogues
//   - paired-independent MMA issue order (j/j+1 interleaved across terms)
// 2-term precision split (A_hi*B_hi + A_hi*B_lo). cp.async double buffer.

#define NSUB 16
#define WID  128
#define NHID 3
#define NSL  (NSUB*NHID)       // 48
#define NPTS 65536
#define NP   128               // points per CTA
#define THREADS 256            // 8 warps x 16 points
#define NCTAS (NPTS/NP)        // 512

#define W_SLOT_BYTES 65536
#define SM_XS (2*W_SLOT_BYTES)
#define SMEM_TOTAL (SM_XS + NP*4)

// Fragment-packed weights: [sl][j(16)][k(8)][lane(32)] x uint4{Bhi0,Bhi1,Blo0,Blo1}
__device__ uint4 g_Wpk[NSL*4096];

// ---------------- helpers ----------------
__device__ __forceinline__ uint32_t smem_u32(const void* p) {
    uint32_t a;
    asm("{ .reg .u64 t; cvta.to.shared.u64 t, %1; cvt.u32.u64 %0, t; }" : "=r"(a) : "l"(p));
    return a;
}
__device__ __forceinline__ float tanhA(float x) {
    float y;
    asm("tanh.approx.f32 %0, %1;" : "=f"(y) : "f"(x));
    return y;
}
__device__ __forceinline__ float fast_sigmoid(float z) {
    return __fdividef(1.0f, 1.0f + __expf(-z));
}
__device__ __forceinline__ uint32_t pack_hi(float f0, float f1) {
    __half2 h = __floats2half2_rn(f0, f1);
    return *reinterpret_cast<uint32_t*>(&h);
}

#define MMA16816(c, a, b0, b1) \
    asm volatile("mma.sync.aligned.m16n8k16.row.col.f32.f16.f16.f32 " \
        "{%0,%1,%2,%3}, {%4,%5,%6,%7}, {%8,%9}, {%0,%1,%2,%3};" \
        : "+f"((c)[0]), "+f"((c)[1]), "+f"((c)[2]), "+f"((c)[3]) \
        : "r"((a)[0]), "r"((a)[1]), "r"((a)[2]), "r"((a)[3]), "r"(b0), "r"(b1))

#define CP_ASYNC16(dst, src) \
    asm volatile("cp.async.cg.shared.global [%0], [%1], 16;" :: "r"(dst), "l"(src) : "memory")
#define CP_COMMIT() asm volatile("cp.async.commit_group;" ::: "memory")
#define CP_WAIT1()  asm volatile("cp.async.wait_group 1;" ::: "memory")

// ---------------- prep: pack weights into fragment order, fp16 hi/lo ----------------
__global__ void prep_pack(const float* __restrict__ Wh) {
    int idx = blockIdx.x * blockDim.x + threadIdx.x;   // < NSL*16*8*32
    int lane = idx & 31;
    int k    = (idx >> 5) & 7;
    int j    = (idx >> 8) & 15;
    int sl   = idx >> 12;
    int g = lane >> 2, t = lane & 3;
    int v = 8 * j + g;              // neuron (n of the mma)
    int w = 16 * k + 2 * t;         // input index (k of the mma)
    const float* row = Wh + ((size_t)sl * WID + v) * WID;
    float w0 = row[w], w1 = row[w + 1], w8 = row[w + 8], w9 = row[w + 9];

    __half2 h01 = __floats2half2_rn(w0, w1);
    __half2 h89 = __floats2half2_rn(w8, w9);
    float l0 = w0 - __low2float(h01), l1 = w1 - __high2float(h01);
    float l8 = w8 - __low2float(h89), l9 = w9 - __high2float(h89);
    __half2 lo01 = __floats2half2_rn(l0, l1);
    __half2 lo89 = __floats2half2_rn(l8, l9);

    uint4 o;
    o.x = *reinterpret_cast<uint32_t*>(&h01);
    o.y = *reinterpret_cast<uint32_t*>(&h89);
    o.z = *reinterpret_cast<uint32_t*>(&lo01);
    o.w = *reinterpret_cast<uint32_t*>(&lo89);
    g_Wpk[idx] = o;
}

// ---------------- stage one layer's packed weights via cp.async ----------------
__device__ __forceinline__ void stage_W(int sl, uint32_t dst_base, int tid) {
    const uint4* src = g_Wpk + (size_t)sl * 4096 + tid;
    uint32_t dst = dst_base + (uint32_t)tid * 16;
    #pragma unroll
    for (int i = 0; i < 16; i++) {
        CP_ASYNC16(dst + (uint32_t)i * 4096u, src + i * 256);
    }
}

// ---------------- main kernel ----------------
__global__ void __launch_bounds__(THREADS, 1) fbpinn_mma_kernel(
    const float* __restrict__ x,
    const float* __restrict__ W0,      // [16,128]
    const float* __restrict__ b0,      // [16,128]
    const float* __restrict__ bh,      // [16,3,128]
    const float* __restrict__ Wout,    // [16,128]
    const float* __restrict__ bout,    // [16]
    const float* __restrict__ centres,
    const float* __restrict__ scales,
    const float* __restrict__ mu_min,
    const float* __restrict__ sd_min,
    const float* __restrict__ mu_max,
    const float* __restrict__ sd_max,
    float* __restrict__ out)
{
    extern __shared__ char smem[];
    const uint32_t sb = smem_u32(smem);
    float* xs = (float*)(smem + SM_XS);

    const int tid  = threadIdx.x;
    const int lane = tid & 31;
    const int w    = tid >> 5;        // warp 0..7
    const int g    = lane >> 2;       // 0..7
    const int t    = lane & 3;        // 0..3
    const int pblk = blockIdx.x * NP;
    const int r0 = w * 16 + g;        // point row (local)
    const int r1 = r0 + 8;

    if (tid < NP) xs[tid] = x[pblk + tid];

    // Prologue: stage sl=0 and sl=1
    stage_W(0, sb, tid);                 CP_COMMIT();
    stage_W(1, sb + W_SLOT_BYTES, tid);  CP_COMMIT();
    __syncthreads();   // xs visible

    const float x0v = xs[r0];
    const float x1v = xs[r1];

    float res0 = 0.0f, res1 = 0.0f;

    uint32_t Ahi[8][4];

    for (int s = 0; s < NSUB; s++) {
        const float centre = __ldg(&centres[s]);
        const float inv_scale = 1.0f / fmaxf(__ldg(&scales[s]), 1e-8f);
        const float xi0 = (x0v - centre) * inv_scale;
        const float xi1 = (x1v - centre) * inv_scale;

        // ---- layer 0: build A fragments directly ----
        const float* W0p = W0 + s * WID;
        const float* b0p = b0 + s * WID;
        #pragma unroll
        for (int kf = 0; kf < 8; kf++) {
            const int vb = 16 * kf + 2 * t;
            const float wv0 = __ldg(&W0p[vb]),     bv0 = __ldg(&b0p[vb]);
            const float wv1 = __ldg(&W0p[vb + 1]), bv1 = __ldg(&b0p[vb + 1]);
            const float wv8 = __ldg(&W0p[vb + 8]), bv8 = __ldg(&b0p[vb + 8]);
            const float wv9 = __ldg(&W0p[vb + 9]), bv9 = __ldg(&b0p[vb + 9]);
            Ahi[kf][0] = pack_hi(tanhA(fmaf(wv0, xi0, bv0)), tanhA(fmaf(wv1, xi0, bv1)));
            Ahi[kf][1] = pack_hi(tanhA(fmaf(wv0, xi1, bv0)), tanhA(fmaf(wv1, xi1, bv1)));
            Ahi[kf][2] = pack_hi(tanhA(fmaf(wv8, xi0, bv8)), tanhA(fmaf(wv9, xi0, bv9)));
            Ahi[kf][3] = pack_hi(tanhA(fmaf(wv8, xi1, bv8)), tanhA(fmaf(wv9, xi1, bv9)));
        }

        // ---- hidden layers ----
        for (int l = 0; l < NHID; l++) {
            const int sl = s * NHID + l;
            const uint32_t slot = sb + (uint32_t)(sl & 1) * W_SLOT_BYTES;

            CP_WAIT1();
            __syncthreads();

            // init acc with bias
            float acc[16][4];
            const float* bhp = bh + sl * WID;
            #pragma unroll
            for (int j = 0; j < 16; j++) {
                const float bv0 = __ldg(&bhp[8 * j + 2 * t]);
                const float bv1 = __ldg(&bhp[8 * j + 2 * t + 1]);
                acc[j][0] = bv0; acc[j][1] = bv1; acc[j][2] = bv0; acc[j][3] = bv1;
            }

            // GEMM: 16 n-tiles x 8 k-steps x 2 terms.
            // Pairs (j, j+1) processed together so consecutive MMAs are independent,
            // with a 2-fragment lookahead to cover LDS latency.
            const uint32_t bbase = (uint32_t)(slot - sb) + ((uint32_t)lane << 4);
            uint4 f0 = *(const uint4*)((const char*)smem + bbase);                 // (j=0,k=0)
            uint4 f1 = *(const uint4*)((const char*)smem + bbase + (1u * 8u << 9)); // (j=1,k=0)
            #pragma unroll
            for (int k = 0; k < 8; k++) {
                #pragma unroll
                for (int j = 0; j < 16; j += 2) {
                    const uint4 c0 = f0, c1 = f1;
                    // next pair: (j+2, k) or (0, k+1); harmless wrap at the very end
                    const int nj = (j == 14) ? 0 : (j + 2);
                    const int nk = (j == 14) ? (k == 7 ? 0 : k + 1) : k;
                    f0 = *(const uint4*)((const char*)smem + bbase + (uint32_t)(((nj    ) * 8 + nk) << 9));
                    f1 = *(const uint4*)((const char*)smem + bbase + (uint32_t)(((nj + 1) * 8 + nk) << 9));
                    MMA16816(acc[j],     Ahi[k], c0.x, c0.y);
                    MMA16816(acc[j + 1], Ahi[k], c1.x, c1.y);
                    MMA16816(acc[j],     Ahi[k], c0.z, c0.w);
                    MMA16816(acc[j + 1], Ahi[k], c1.z, c1.w);
                }
            }

            __syncthreads();   // all warps done reading this slot
            if (sl + 2 < NSL) stage_W(sl + 2, slot, tid);
            CP_COMMIT();

            if (l < NHID - 1) {
                // epilogue: hardware tanh -> fp16 -> next A fragments
                #pragma unroll
                for (int kf = 0; kf < 8; kf++) {
                    const int j0 = 2 * kf, j1 = 2 * kf + 1;
                    Ahi[kf][0] = pack_hi(tanhA(acc[j0][0]), tanhA(acc[j0][1]));
                    Ahi[kf][1] = pack_hi(tanhA(acc[j0][2]), tanhA(acc[j0][3]));
                    Ahi[kf][2] = pack_hi(tanhA(acc[j1][0]), tanhA(acc[j1][1]));
                    Ahi[kf][3] = pack_hi(tanhA(acc[j1][2]), tanhA(acc[j1][3]));
                }
            } else {
                // final: fold output layer + window
                float p0 = 0.0f, p1 = 0.0f;
                const float* wop = Wout + s * WID;
                #pragma unroll
                for (int j = 0; j < 16; j++) {
                    const float wv0 = __ldg(&wop[8 * j + 2 * t]);
                    const float wv1 = __ldg(&wop[8 * j + 2 * t + 1]);
                    p0 = fmaf(wv0, tanhA(acc[j][0]), p0);
                    p0 = fmaf(wv1, tanhA(acc[j][1]), p0);
                    p1 = fmaf(wv0, tanhA(acc[j][2]), p1);
                    p1 = fmaf(wv1, tanhA(acc[j][3]), p1);
                }
                p0 += __shfl_xor_sync(0xFFFFFFFF, p0, 1);
                p0 += __shfl_xor_sync(0xFFFFFFFF, p0, 2);
                p1 += __shfl_xor_sync(0xFFFFFFFF, p1, 1);
                p1 += __shfl_xor_sync(0xFFFFFFFF, p1, 2);

                const float bo = __ldg(&bout[s]);
                const float mmin = __ldg(&mu_min[s]), smin = __ldg(&sd_min[s]);
                const float mmax = __ldg(&mu_max[s]), smax = __ldg(&sd_max[s]);
                const float wm0 = fast_sigmoid((x0v - mmin) / smin) *
                                  fast_sigmoid((mmax - x0v) / smax);
                const float wm1 = fast_sigmoid((x1v - mmin) / smin) *
                                  fast_sigmoid((mmax - x1v) / smax);
                res0 = fmaf(wm0, p0 + bo, res0);
                res1 = fmaf(wm1, p1 + bo, res1);
            }
        }
    }

    if (t == 0) {
        out[pblk + r0] = res0;
        out[pblk + r1] = res1;
    }
}

// ---------------- launch ----------------
extern "C" void kernel_launch(void* const* d_in, const int* in_sizes, int n_in,
                              void* d_out, int out_size) {
    const float* x       = (const float*)d_in[0];
    const float* W0      = (const float*)d_in[1];
    const float* b0      = (const float*)d_in[2];
    const float* Wh      = (const float*)d_in[3];
    const float* bh      = (const float*)d_in[4];
    const float* Wout    = (const float*)d_in[5];
    const float* bout    = (const float*)d_in[6];
    const float* centres = (const float*)d_in[7];
    const float* scales  = (const float*)d_in[8];
    const float* mu_min  = (const float*)d_in[9];
    const float* sd_min  = (const float*)d_in[10];
    const float* mu_max  = (const float*)d_in[11];
    const float* sd_max  = (const float*)d_in[12];
    float* out = (float*)d_out;

    cudaFuncSetAttribute(fbpinn_mma_kernel,
                         cudaFuncAttributeMaxDynamicSharedMemorySize, SMEM_TOTAL);

    prep_pack<<<(NSL * 4096) / 256, 256>>>(Wh);

    fbpinn_mma_kernel<<<NCTAS, THREADS, SMEM_TOTAL>>>(
        x, W0, b0, bh, Wout, bout, centres, scales,
        mu_min, sd_min, mu_max, sd_max, out);
}